// round 7
// baseline (speedup 1.0000x reference)
#include <cuda_runtime.h>
#include <math.h>

#define NMAX 100000
#define EMAX 3200000
#define ETMAX (EMAX + NMAX)

// ---------- scratch ----------
__device__ __align__(16) float d_h1 [NMAX * 32];
__device__ __align__(16) float d_as1[NMAX * 4];
__device__ __align__(16) float d_ad1[NMAX * 4];
__device__ __align__(16) float d_out1[NMAX * 32];

__device__ __align__(16) float4 d_p2s[NMAX];   // {g0, g1, as2, unused}
__device__ __align__(16) float  d_ad2[NMAX];

// CSR by dst
__device__ __align__(16) int  d_count[NMAX];
__device__ __align__(16) int  d_start[NMAX];
__device__ __align__(16) int  d_fill [NMAX];
__device__ __align__(16) int2 d_csr  [ETMAX];   // {src, orig edge id}
__device__ int d_cursor;

__device__ __forceinline__ float lrelu(float v) { return v > 0.0f ? v : 0.2f * v; }

__device__ __forceinline__ void edge_sd(const int* __restrict__ ei, int i, int E,
                                        int& s, int& d) {
    if (i < E) { s = ei[i]; d = ei[E + i]; }
    else       { s = i - E; d = i - E; }
}

// ---------- CSR build ----------
__global__ void k_zero(int N) {
    int n = blockIdx.x * blockDim.x + threadIdx.x;
    if (n < N) { d_count[n] = 0; d_fill[n] = 0; }
    if (n == 0) d_cursor = 0;
}

__global__ void k_hist(const int* __restrict__ ei, int E, int ET) {
    int i = blockIdx.x * blockDim.x + threadIdx.x;
    if (i >= ET) return;
    int d = (i < E) ? ei[E + i] : i - E;
    atomicAdd(&d_count[d], 1);
}

// disjoint row allocation: block scan + one global cursor bump per block.
// (ordering of rows is irrelevant -> no deterministic prefix sum needed)
__global__ void k_alloc(int N) {
    __shared__ int sh[256];
    __shared__ int base;
    int t = threadIdx.x;
    int n = blockIdx.x * 256 + t;
    int c = (n < N) ? d_count[n] : 0;
    sh[t] = c;
    __syncthreads();
#pragma unroll
    for (int off = 1; off < 256; off <<= 1) {
        int v = (t >= off) ? sh[t - off] : 0;
        __syncthreads();
        sh[t] += v;
        __syncthreads();
    }
    if (t == 255) base = atomicAdd(&d_cursor, sh[255]);
    __syncthreads();
    if (n < N) d_start[n] = base + sh[t] - c;   // exclusive
}

__global__ void k_fill(const int* __restrict__ ei, int E, int ET) {
    int i = blockIdx.x * blockDim.x + threadIdx.x;
    if (i >= ET) return;
    int s, d; edge_sd(ei, i, E, s, d);
    int pos = d_start[d] + atomicAdd(&d_fill[d], 1);
    d_csr[pos] = make_int2(s, i);
}

// ---------- layer 1: node transform ----------
__global__ void k_node1(const float* __restrict__ x, const float* __restrict__ W1,
                        const float* __restrict__ asr, const float* __restrict__ adr, int N) {
    int n = blockIdx.x * blockDim.x + threadIdx.x;
    if (n >= N) return;
    float x0 = x[2 * n], x1 = x[2 * n + 1];
    float h[32];
#pragma unroll
    for (int k = 0; k < 32; k++) h[k] = x0 * W1[k] + x1 * W1[32 + k];
#pragma unroll
    for (int hh = 0; hh < 4; hh++) {
        float s = 0.f, d = 0.f;
#pragma unroll
        for (int c = 0; c < 8; c++) {
            s += h[hh * 8 + c] * asr[hh * 8 + c];
            d += h[hh * 8 + c] * adr[hh * 8 + c];
        }
        d_as1[n * 4 + hh] = s;
        d_ad1[n * 4 + hh] = d;
    }
#pragma unroll
    for (int k = 0; k < 32; k++) d_h1[n * 32 + k] = h[k];
}

// ---------- layer 1: softmax + aggregate, one warp per dst node, NO atomics ----------
__global__ void k_conv1(float* __restrict__ alpha_out, int N) {
    int warp = (blockIdx.x * blockDim.x + threadIdx.x) >> 5;
    if (warp >= N) return;
    int n = warp;
    int lane = threadIdx.x & 31;
    int h = lane >> 3;                  // head for this lane's channel
    int base = d_start[n], deg = d_count[n];
    float ad = d_ad1[n * 4 + h];

    // phase 1: softmax denominator (same value across each 8-lane group)
    float ssum = 0.f;
    for (int e = 0; e < deg; e++) {
        int2 p = d_csr[base + e];       // warp-uniform load
        float as = d_as1[p.x * 4 + h];
        ssum += __expf(lrelu(as + ad));
    }
    float inv = 1.0f / (ssum + 1e-16f);

    // phase 2: normalize + aggregate (exp recomputed bit-identically)
    float acc = 0.f;
    for (int e = 0; e < deg; e++) {
        int2 p = d_csr[base + e];
        float as = d_as1[p.x * 4 + h];
        float al = __expf(lrelu(as + ad)) * inv;
        if (alpha_out && (lane & 7) == 0) alpha_out[p.y * 4 + h] = al;
        acc += d_h1[p.x * 32 + lane] * al;   // coalesced: 1 line per edge
    }
    d_out1[n * 32 + lane] = acc;             // single coalesced row store
}

// ---------- layer 2: node transform ----------
__global__ void k_node2(const float* __restrict__ b1, const float* __restrict__ W2,
                        const float* __restrict__ asr, const float* __restrict__ adr, int N) {
    int n = blockIdx.x * blockDim.x + threadIdx.x;
    if (n >= N) return;
    float g0 = 0.f, g1 = 0.f;
#pragma unroll
    for (int k = 0; k < 32; k++) {
        float v = d_out1[n * 32 + k] + b1[k];
        v = v > 0.f ? v : expm1f(v);
        g0 += v * W2[k * 2];
        g1 += v * W2[k * 2 + 1];
    }
    d_p2s[n] = make_float4(g0, g1, g0 * asr[0] + g1 * asr[1], 0.f);
    d_ad2[n] = g0 * adr[0] + g1 * adr[1];
}

// ---------- layer 2: softmax + aggregate + bias, 8 lanes per dst node ----------
__global__ void k_conv2(float* __restrict__ out, float* __restrict__ alpha_out,
                        const float* __restrict__ b2, int N) {
    int t = blockIdx.x * blockDim.x + threadIdx.x;
    int n = t >> 3;
    if (n >= N) return;
    int l8 = t & 7;
    int base = d_start[n], deg = d_count[n];
    float ad = d_ad2[n];

    float ssum = 0.f;
    for (int e = l8; e < deg; e += 8) {
        float as = d_p2s[d_csr[base + e].x].z;
        ssum += __expf(lrelu(as + ad));
    }
#pragma unroll
    for (int o = 4; o >= 1; o >>= 1) ssum += __shfl_xor_sync(0xffffffffu, ssum, o, 8);
    float inv = 1.0f / (ssum + 1e-16f);

    float ax = 0.f, ay = 0.f;
    for (int e = l8; e < deg; e += 8) {
        int2 p = d_csr[base + e];
        float4 ps = d_p2s[p.x];
        float al = __expf(lrelu(ps.z + ad)) * inv;
        if (alpha_out) alpha_out[p.y] = al;
        ax += ps.x * al;
        ay += ps.y * al;
    }
#pragma unroll
    for (int o = 4; o >= 1; o >>= 1) {
        ax += __shfl_xor_sync(0xffffffffu, ax, o, 8);
        ay += __shfl_xor_sync(0xffffffffu, ay, o, 8);
    }
    if (l8 == 0) {
        out[n * 2]     = ax + b2[0];
        out[n * 2 + 1] = ay + b2[1];
    }
}

// ---------- tail fill: zero any region not written elsewhere ----------
__global__ void k_tail(float* __restrict__ out, int lo, int hi) {
    int i = lo + blockIdx.x * blockDim.x + threadIdx.x;
    if (i < hi) out[i] = 0.f;
}

extern "C" void kernel_launch(void* const* d_in, const int* in_sizes, int n_in,
                              void* d_out, int out_size) {
    const float* x   = (const float*)d_in[0];
    const int*   ei  = (const int*)d_in[1];   // edge_index stored as int32 by harness
    // d_in[2] = edge_attr (ignored by reference)
    const float* W1   = (const float*)d_in[3];
    const float* as1  = (const float*)d_in[4];
    const float* ad1  = (const float*)d_in[5];
    const float* b1   = (const float*)d_in[6];
    const float* W2   = (const float*)d_in[7];
    const float* as2  = (const float*)d_in[8];
    const float* ad2  = (const float*)d_in[9];
    const float* b2   = (const float*)d_in[10];
    float* out = (float*)d_out;

    int N  = in_sizes[0] / 2;
    int E  = in_sizes[1] / 2;
    int ET = E + N;
    long long total = (long long)N * 2 + (long long)ET * 5;
    bool full = (out_size >= total);

    float* alpha1_out = full ? out + (size_t)N * 2 : nullptr;
    float* alpha2_out = full ? out + (size_t)N * 2 + (size_t)ET * 4 : nullptr;

    const int T = 256;
    int gN   = (N  + T - 1) / T;
    int gET  = (ET + T - 1) / T;
    int gW   = (N * 32 + T - 1) / T;   // warp per node
    int gN8  = (N * 8  + T - 1) / T;   // 8 lanes per node

    // CSR build (row order nondeterministic; results order-invariant within tol)
    k_zero<<<gN, T>>>(N);
    k_hist<<<gET, T>>>(ei, E, ET);
    k_alloc<<<gN, T>>>(N);
    k_fill<<<gET, T>>>(ei, E, ET);

    // layer 1
    k_node1<<<gN, T>>>(x, W1, as1, ad1, N);
    k_conv1<<<gW, T>>>(alpha1_out, N);

    // layer 2 (writes final out rows + bias directly)
    k_node2<<<gN, T>>>(b1, W2, as2, ad2, N);
    k_conv2<<<gN8, T>>>(out, alpha2_out, b2, N);

    // zero any unwritten tail region
    int lo = full ? (int)total : N * 2;
    if (out_size > lo) {
        int cnt = out_size - lo;
        k_tail<<<(cnt + T - 1) / T, T>>>(out, lo, out_size);
    }
}

// round 8
// speedup vs baseline: 1.0925x; 1.0925x over previous
#include <cuda_runtime.h>
#include <math.h>

#define NMAX 100000
#define EMAX 3200000
#define ETMAX (EMAX + NMAX)

// ---------- scratch ----------
__device__ __align__(16) float d_h1 [NMAX * 32];
__device__ __align__(16) float d_as1[NMAX * 4];
__device__ __align__(16) float d_ad1[NMAX * 4];
__device__ __align__(16) float d_out1[NMAX * 32];

__device__ __align__(16) float4 d_p2s[NMAX];   // {g0, g1, as2, unused}
__device__ __align__(16) float  d_ad2[NMAX];

// CSR by dst
__device__ __align__(16) int  d_count[NMAX];
__device__ __align__(16) int  d_start[NMAX];
__device__ __align__(16) int  d_fill [NMAX];
__device__ __align__(16) int2 d_csr  [ETMAX];   // {src, orig edge id}
__device__ int d_cursor;

__device__ __forceinline__ float lrelu(float v) { return v > 0.0f ? v : 0.2f * v; }

__device__ __forceinline__ void edge_sd(const int* __restrict__ ei, int i, int E,
                                        int& s, int& d) {
    if (i < E) { s = ei[i]; d = ei[E + i]; }
    else       { s = i - E; d = i - E; }
}

// ---------- CSR build ----------
__global__ void k_zero(int N) {
    int n = blockIdx.x * blockDim.x + threadIdx.x;
    if (n < N) { d_count[n] = 0; d_fill[n] = 0; }
    if (n == 0) d_cursor = 0;
}

__global__ void k_hist(const int* __restrict__ ei, int E, int ET) {
    int i = blockIdx.x * blockDim.x + threadIdx.x;
    if (i >= ET) return;
    int d = (i < E) ? ei[E + i] : i - E;
    atomicAdd(&d_count[d], 1);
}

// disjoint row allocation: block scan + one global cursor bump per block.
__global__ void k_alloc(int N) {
    __shared__ int sh[256];
    __shared__ int base;
    int t = threadIdx.x;
    int n = blockIdx.x * 256 + t;
    int c = (n < N) ? d_count[n] : 0;
    sh[t] = c;
    __syncthreads();
#pragma unroll
    for (int off = 1; off < 256; off <<= 1) {
        int v = (t >= off) ? sh[t - off] : 0;
        __syncthreads();
        sh[t] += v;
        __syncthreads();
    }
    if (t == 255) base = atomicAdd(&d_cursor, sh[255]);
    __syncthreads();
    if (n < N) d_start[n] = base + sh[t] - c;   // exclusive
}

__global__ void k_fill(const int* __restrict__ ei, int E, int ET) {
    int i = blockIdx.x * blockDim.x + threadIdx.x;
    if (i >= ET) return;
    int s, d; edge_sd(ei, i, E, s, d);
    int pos = d_start[d] + atomicAdd(&d_fill[d], 1);
    d_csr[pos] = make_int2(s, i);
}

// ---------- layer 1: node transform ----------
__global__ void k_node1(const float* __restrict__ x, const float* __restrict__ W1,
                        const float* __restrict__ asr, const float* __restrict__ adr, int N) {
    int n = blockIdx.x * blockDim.x + threadIdx.x;
    if (n >= N) return;
    float x0 = x[2 * n], x1 = x[2 * n + 1];
    float h[32];
#pragma unroll
    for (int k = 0; k < 32; k++) h[k] = x0 * W1[k] + x1 * W1[32 + k];
#pragma unroll
    for (int hh = 0; hh < 4; hh++) {
        float s = 0.f, d = 0.f;
#pragma unroll
        for (int c = 0; c < 8; c++) {
            s += h[hh * 8 + c] * asr[hh * 8 + c];
            d += h[hh * 8 + c] * adr[hh * 8 + c];
        }
        d_as1[n * 4 + hh] = s;
        d_ad1[n * 4 + hh] = d;
    }
#pragma unroll
    for (int k = 0; k < 32; k++) d_h1[n * 32 + k] = h[k];
}

// ---------- layer 1: softmax + aggregate, one warp per dst node, NO atomics ----------
// phase 1 parallelized 8x: lane l8 handles edges e = l8, l8+8, ... then
// shfl_xor reduction within each 8-lane (per-head) group.
__global__ void k_conv1(float* __restrict__ alpha_out, int N) {
    int warp = (blockIdx.x * blockDim.x + threadIdx.x) >> 5;
    if (warp >= N) return;
    int n = warp;
    int lane = threadIdx.x & 31;
    int l8 = lane & 7;
    int h = lane >> 3;                  // head for this lane's channel
    int base = d_start[n], deg = d_count[n];
    float ad = d_ad1[n * 4 + h];

    // phase 1: softmax denominator, 8 edges in flight per head-group
    float ssum = 0.f;
    for (int e = l8; e < deg; e += 8) {
        int s = d_csr[base + e].x;      // 8 consecutive int2 across lanes: 64B
        ssum += __expf(lrelu(d_as1[s * 4 + h] + ad));
    }
#pragma unroll
    for (int o = 4; o >= 1; o >>= 1) ssum += __shfl_xor_sync(0xffffffffu, ssum, o, 8);
    float inv = 1.0f / (ssum + 1e-16f);

    // phase 2: normalize + aggregate, lane owns channel `lane`
    float acc = 0.f;
#pragma unroll 2
    for (int e = 0; e < deg; e++) {
        int2 p = d_csr[base + e];
        float al = __expf(lrelu(d_as1[p.x * 4 + h] + ad)) * inv;
        if (alpha_out && l8 == 0) alpha_out[p.y * 4 + h] = al;
        acc += d_h1[p.x * 32 + lane] * al;   // coalesced: 1 line per edge
    }
    d_out1[n * 32 + lane] = acc;             // single coalesced row store
}

// ---------- layer 2: node transform, 8 lanes per node (coalesced) ----------
__global__ void k_node2(const float* __restrict__ b1, const float* __restrict__ W2,
                        const float* __restrict__ asr, const float* __restrict__ adr, int N) {
    int t = blockIdx.x * blockDim.x + threadIdx.x;
    int n = t >> 3;
    if (n >= N) return;
    int l = t & 7;
    float4 v = ((const float4*)d_out1)[n * 8 + l];   // coalesced 128B per 8 lanes
    float4 bb = ((const float4*)b1)[l];
    float c0 = v.x + bb.x, c1 = v.y + bb.y, c2 = v.z + bb.z, c3 = v.w + bb.w;
    c0 = c0 > 0.f ? c0 : expm1f(c0);
    c1 = c1 > 0.f ? c1 : expm1f(c1);
    c2 = c2 > 0.f ? c2 : expm1f(c2);
    c3 = c3 > 0.f ? c3 : expm1f(c3);
    int k = l * 4;
    float g0 = c0 * W2[k * 2]     + c1 * W2[k * 2 + 2] + c2 * W2[k * 2 + 4] + c3 * W2[k * 2 + 6];
    float g1 = c0 * W2[k * 2 + 1] + c1 * W2[k * 2 + 3] + c2 * W2[k * 2 + 5] + c3 * W2[k * 2 + 7];
#pragma unroll
    for (int o = 4; o >= 1; o >>= 1) {
        g0 += __shfl_xor_sync(0xffffffffu, g0, o, 8);
        g1 += __shfl_xor_sync(0xffffffffu, g1, o, 8);
    }
    if (l == 0) {
        d_p2s[n] = make_float4(g0, g1, g0 * asr[0] + g1 * asr[1], 0.f);
        d_ad2[n] = g0 * adr[0] + g1 * adr[1];
    }
}

// ---------- layer 2: softmax + aggregate + bias, 8 lanes per dst node ----------
__global__ void k_conv2(float* __restrict__ out, float* __restrict__ alpha_out,
                        const float* __restrict__ b2, int N) {
    int t = blockIdx.x * blockDim.x + threadIdx.x;
    int n = t >> 3;
    if (n >= N) return;
    int l8 = t & 7;
    int base = d_start[n], deg = d_count[n];
    float ad = d_ad2[n];

    float ssum = 0.f;
    for (int e = l8; e < deg; e += 8) {
        float as = d_p2s[d_csr[base + e].x].z;
        ssum += __expf(lrelu(as + ad));
    }
#pragma unroll
    for (int o = 4; o >= 1; o >>= 1) ssum += __shfl_xor_sync(0xffffffffu, ssum, o, 8);
    float inv = 1.0f / (ssum + 1e-16f);

    float ax = 0.f, ay = 0.f;
    for (int e = l8; e < deg; e += 8) {
        int2 p = d_csr[base + e];
        float4 ps = d_p2s[p.x];
        float al = __expf(lrelu(ps.z + ad)) * inv;
        if (alpha_out) alpha_out[p.y] = al;
        ax += ps.x * al;
        ay += ps.y * al;
    }
#pragma unroll
    for (int o = 4; o >= 1; o >>= 1) {
        ax += __shfl_xor_sync(0xffffffffu, ax, o, 8);
        ay += __shfl_xor_sync(0xffffffffu, ay, o, 8);
    }
    if (l8 == 0) {
        out[n * 2]     = ax + b2[0];
        out[n * 2 + 1] = ay + b2[1];
    }
}

// ---------- tail fill: zero any region not written elsewhere ----------
__global__ void k_tail(float* __restrict__ out, int lo, int hi) {
    int i = lo + blockIdx.x * blockDim.x + threadIdx.x;
    if (i < hi) out[i] = 0.f;
}

extern "C" void kernel_launch(void* const* d_in, const int* in_sizes, int n_in,
                              void* d_out, int out_size) {
    const float* x   = (const float*)d_in[0];
    const int*   ei  = (const int*)d_in[1];   // edge_index stored as int32 by harness
    // d_in[2] = edge_attr (ignored by reference)
    const float* W1   = (const float*)d_in[3];
    const float* as1  = (const float*)d_in[4];
    const float* ad1  = (const float*)d_in[5];
    const float* b1   = (const float*)d_in[6];
    const float* W2   = (const float*)d_in[7];
    const float* as2  = (const float*)d_in[8];
    const float* ad2  = (const float*)d_in[9];
    const float* b2   = (const float*)d_in[10];
    float* out = (float*)d_out;

    int N  = in_sizes[0] / 2;
    int E  = in_sizes[1] / 2;
    int ET = E + N;
    long long total = (long long)N * 2 + (long long)ET * 5;
    bool full = (out_size >= total);

    float* alpha1_out = full ? out + (size_t)N * 2 : nullptr;
    float* alpha2_out = full ? out + (size_t)N * 2 + (size_t)ET * 4 : nullptr;

    const int T = 256;
    int gN   = (N  + T - 1) / T;
    int gET  = (ET + T - 1) / T;
    int gW   = (N * 32 + T - 1) / T;   // warp per node
    int gN8  = (N * 8  + T - 1) / T;   // 8 lanes per node

    // CSR build (row order nondeterministic; results order-invariant within tol)
    k_zero<<<gN, T>>>(N);
    k_hist<<<gET, T>>>(ei, E, ET);
    k_alloc<<<gN, T>>>(N);
    k_fill<<<gET, T>>>(ei, E, ET);

    // layer 1
    k_node1<<<gN, T>>>(x, W1, as1, ad1, N);
    k_conv1<<<gW, T>>>(alpha1_out, N);

    // layer 2 (writes final out rows + bias directly)
    k_node2<<<gN8, T>>>(b1, W2, as2, ad2, N);
    k_conv2<<<gN8, T>>>(out, alpha2_out, b2, N);

    // zero any unwritten tail region
    int lo = full ? (int)total : N * 2;
    if (out_size > lo) {
        int cnt = out_size - lo;
        k_tail<<<(cnt + T - 1) / T, T>>>(out, lo, out_size);
    }
}